// round 1
// baseline (speedup 1.0000x reference)
#include <cuda_runtime.h>
#include <math.h>

#define NB 16
#define T1V 800
#define T2V 200

// Intermediates (no allocation allowed -> __device__ globals)
__device__ float g_kh [NB*512*200];   // key conv1 output (post-relu)
__device__ float g_k  [NB*80*200];    // key encoder output
__device__ float g_qh1[NB*160*800];   // query conv1 output (post-relu)
__device__ float g_qh2[NB*80*800];    // query conv2 output (post-relu)
__device__ float g_q  [NB*80*800];    // query encoder output

// Implicit-im2col conv-as-GEMM.
//   Y[b, m, t] = bias[m] + sum_{cin,kk} W[m, cin, kk] * X[b, cin, t+kk-PAD]
// GEMM: M = COUT, N = NB*T, K = CIN*KW (kappa = kk*CIN + cin).
// Block: 256 threads as 16x16, thread tile TM x TN, block tile (16*TM) x (16*TN), BK=16.
// All instantiations chosen so M % BM == 0, N % BN == 0, K % BK == 0.
template<int CIN, int COUT, int KW, int PAD, bool RELU, int TM, int TN, int T>
__global__ __launch_bounds__(256)
void conv_gemm(const float* __restrict__ W, const float* __restrict__ bias,
               const float* __restrict__ X, float* __restrict__ Y)
{
    constexpr int BM = 16 * TM, BN = 16 * TN, BK = 16;
    constexpr int K  = CIN * KW;
    constexpr int LA = (BK * BM) / 256;
    constexpr int LB = (BK * BN) / 256;

    __shared__ float As[BK][BM + 4];
    __shared__ float Bs[BK][BN];

    const int tid = threadIdx.x;
    const int tx  = tid & 15, ty = tid >> 4;
    const int n0  = blockIdx.x * BN;
    const int m0  = blockIdx.y * BM;

    // Precompute per-thread load slots (fixed across K-chunks).
    int a_kl[LA], a_m[LA];
#pragma unroll
    for (int s = 0; s < LA; s++) {
        int i = tid + s * 256;
        a_kl[s] = i % BK;        // consecutive tid -> consecutive kappa (coalesced-ish W reads)
        a_m [s] = i / BK;
    }
    int b_kl[LB], b_n[LB], b_t[LB], b_row[LB];
#pragma unroll
    for (int s = 0; s < LB; s++) {
        int i = tid + s * 256;
        b_kl[s] = i / BN;
        int n   = i % BN;
        b_n[s]  = n;
        int gn  = n0 + n;
        int bb  = gn / T;        // column may cross batch boundary; decode per column
        b_t[s]  = gn - bb * T;
        b_row[s]= bb * CIN * T;
    }

    float acc[TM][TN];
#pragma unroll
    for (int i = 0; i < TM; i++)
#pragma unroll
        for (int j = 0; j < TN; j++) acc[i][j] = 0.f;

    for (int k0 = 0; k0 < K; k0 += BK) {
#pragma unroll
        for (int s = 0; s < LA; s++) {
            int kap = k0 + a_kl[s];
            int kk  = kap / CIN;
            int cin = kap - kk * CIN;
            As[a_kl[s]][a_m[s]] = W[(m0 + a_m[s]) * K + cin * KW + kk];
        }
#pragma unroll
        for (int s = 0; s < LB; s++) {
            int kap = k0 + b_kl[s];
            int kk  = kap / CIN;
            int cin = kap - kk * CIN;
            int tin = b_t[s] + kk - PAD;
            float v = 0.f;
            if ((unsigned)tin < (unsigned)T)
                v = X[b_row[s] + cin * T + tin];
            Bs[b_kl[s]][b_n[s]] = v;
        }
        __syncthreads();
#pragma unroll
        for (int kl = 0; kl < BK; kl++) {
            float a[TM], bv[TN];
#pragma unroll
            for (int i = 0; i < TM; i++) a[i] = As[kl][ty * TM + i];
#pragma unroll
            for (int j = 0; j < TN; j++) bv[j] = Bs[kl][tx * TN + j];
#pragma unroll
            for (int i = 0; i < TM; i++)
#pragma unroll
                for (int j = 0; j < TN; j++)
                    acc[i][j] += a[i] * bv[j];
        }
        __syncthreads();
    }

#pragma unroll
    for (int j = 0; j < TN; j++) {
        int gn  = n0 + tx * TN + j;
        int bb2 = gn / T;
        int tt  = gn - bb2 * T;
#pragma unroll
        for (int i = 0; i < TM; i++) {
            int m   = m0 + ty * TM + i;
            float v = acc[i][j] + bias[m];
            if (RELU) v = fmaxf(v, 0.f);
            Y[(bb2 * COUT + m) * T + tt] = v;
        }
    }
}

// Final fused kernel: per (batch, 32 t1 rows):
//   logits[t1,t2] = -5e-4 * (|q|^2 + |k|^2 - 2 q.k)
//   out = logits - logsumexp_t2(logits) + log(prior + 1e-8)
// Each thread: 2 t1 rows x 13 t2 columns (t2 = cg + 16j). Row reductions via
// half-warp shuffles (16 threads per row-pair, all in the same half-warp).
__global__ __launch_bounds__(256)
void attn_final(const float* __restrict__ q, const float* __restrict__ k,
                const float* __restrict__ prior, float* __restrict__ out)
{
    extern __shared__ float sm[];
    float* ksh  = sm;                 // [80][200] = 16000
    float* qsh  = sm + 16000;         // [32][81]  =  2592 (padded: conflict-free transposed store)
    float* k2sh = qsh + 32 * 81;      // [200]
    float* q2sh = k2sh + 200;         // [32]

    const int b   = blockIdx.y;
    const int t10 = blockIdx.x * 32;
    const int tid = threadIdx.x;

    for (int i = tid; i < 80 * 200; i += 256)
        ksh[i] = k[b * 16000 + i];
    for (int i = tid; i < 80 * 32; i += 256) {
        int c = i >> 5, tl = i & 31;
        qsh[tl * 81 + c] = q[(b * 80 + c) * 800 + t10 + tl];
    }
    __syncthreads();

    if (tid < 200) {
        float s = 0.f;
#pragma unroll
        for (int c = 0; c < 80; c++) { float v = ksh[c * 200 + tid]; s += v * v; }
        k2sh[tid] = s;
    }
    if (tid < 32) {
        float s = 0.f;
#pragma unroll
        for (int c = 0; c < 80; c++) { float v = qsh[tid * 81 + c]; s += v * v; }
        q2sh[tid] = s;
    }
    __syncthreads();

    const int r0 = (tid >> 4) * 2;   // two t1 rows per thread
    const int cg = tid & 15;

    float acc0[13], acc1[13];
#pragma unroll
    for (int j = 0; j < 13; j++) { acc0[j] = 0.f; acc1[j] = 0.f; }

#pragma unroll 4
    for (int c = 0; c < 80; c++) {
        float q0 = qsh[r0 * 81 + c];
        float q1 = qsh[(r0 + 1) * 81 + c];
#pragma unroll
        for (int j = 0; j < 13; j++) {
            // j==12, cg>=8 reads stale in-bounds smem; result discarded below.
            float kv = ksh[c * 200 + cg + 16 * j];
            acc0[j] += q0 * kv;
            acc1[j] += q1 * kv;
        }
    }

    float q20 = q2sh[r0], q21 = q2sh[r0 + 1];
    float mx0 = -1e30f, mx1 = -1e30f;
#pragma unroll
    for (int j = 0; j < 13; j++) {
        int t2 = cg + 16 * j;
        if (t2 < 200) {
            acc0[j] = -5e-4f * (q20 + k2sh[t2] - 2.f * acc0[j]);
            acc1[j] = -5e-4f * (q21 + k2sh[t2] - 2.f * acc1[j]);
            mx0 = fmaxf(mx0, acc0[j]);
            mx1 = fmaxf(mx1, acc1[j]);
        }
    }
#pragma unroll
    for (int o = 8; o >= 1; o >>= 1) {
        mx0 = fmaxf(mx0, __shfl_xor_sync(0xFFFFFFFFu, mx0, o, 16));
        mx1 = fmaxf(mx1, __shfl_xor_sync(0xFFFFFFFFu, mx1, o, 16));
    }
    float s0 = 0.f, s1 = 0.f;
#pragma unroll
    for (int j = 0; j < 13; j++) {
        int t2 = cg + 16 * j;
        if (t2 < 200) {
            s0 += __expf(acc0[j] - mx0);
            s1 += __expf(acc1[j] - mx1);
        }
    }
#pragma unroll
    for (int o = 8; o >= 1; o >>= 1) {
        s0 += __shfl_xor_sync(0xFFFFFFFFu, s0, o, 16);
        s1 += __shfl_xor_sync(0xFFFFFFFFu, s1, o, 16);
    }
    float l0 = mx0 + logf(s0);
    float l1 = mx1 + logf(s1);

    int base0 = (b * T1V + t10 + r0) * T2V;
    int base1 = base0 + T2V;
#pragma unroll
    for (int j = 0; j < 13; j++) {
        int t2 = cg + 16 * j;
        if (t2 < 200) {
            out[base0 + t2] = acc0[j] - l0 + logf(prior[base0 + t2] + 1e-8f);
            out[base1 + t2] = acc1[j] - l1 + logf(prior[base1 + t2] + 1e-8f);
        }
    }
}

extern "C" void kernel_launch(void* const* d_in, const int* in_sizes, int n_in,
                              void* d_out, int out_size)
{
    const float* queries = (const float*)d_in[0];   // (16, 80, 800)
    const float* keys    = (const float*)d_in[1];   // (16, 256, 200)
    const float* prior   = (const float*)d_in[2];   // (16, 800, 200)
    const float* kw1 = (const float*)d_in[3];       // (512, 256, 3)
    const float* kb1 = (const float*)d_in[4];
    const float* kw2 = (const float*)d_in[5];       // (80, 512, 1)
    const float* kb2 = (const float*)d_in[6];
    const float* qw1 = (const float*)d_in[7];       // (160, 80, 3)
    const float* qb1 = (const float*)d_in[8];
    const float* qw2 = (const float*)d_in[9];       // (80, 160, 1)
    const float* qb2 = (const float*)d_in[10];
    const float* qw3 = (const float*)d_in[11];      // (80, 80, 1)
    const float* qb3 = (const float*)d_in[12];
    float* out = (float*)d_out;

    float *p_kh, *p_k, *p_qh1, *p_qh2, *p_q;
    cudaGetSymbolAddress((void**)&p_kh,  g_kh);
    cudaGetSymbolAddress((void**)&p_k,   g_k);
    cudaGetSymbolAddress((void**)&p_qh1, g_qh1);
    cudaGetSymbolAddress((void**)&p_qh2, g_qh2);
    cudaGetSymbolAddress((void**)&p_q,   g_q);

    // Key encoder: conv(256->512,k3,p1)+relu ; conv(512->80,k1)
    conv_gemm<256, 512, 3, 1, true,  8, 4, 200><<<dim3(50, 4),  256>>>(kw1, kb1, keys,  p_kh);
    conv_gemm<512,  80, 1, 0, false, 5, 2, 200><<<dim3(100, 1), 256>>>(kw2, kb2, p_kh,  p_k);
    // Query encoder: conv(80->160,k3,p1)+relu ; conv(160->80)+relu ; conv(80->80)
    conv_gemm< 80, 160, 3, 1, true,  5, 4, 800><<<dim3(200, 2), 256>>>(qw1, qb1, queries, p_qh1);
    conv_gemm<160,  80, 1, 0, true,  5, 4, 800><<<dim3(200, 1), 256>>>(qw2, qb2, p_qh1, p_qh2);
    conv_gemm< 80,  80, 1, 0, false, 5, 4, 800><<<dim3(200, 1), 256>>>(qw3, qb3, p_qh2, p_q);

    // Fused distance + log-softmax + prior
    const int smem = (16000 + 32 * 81 + 200 + 32) * (int)sizeof(float);  // 75296 B
    cudaFuncSetAttribute(attn_final, cudaFuncAttributeMaxDynamicSharedMemorySize, smem);
    attn_final<<<dim3(25, 16), 256, smem>>>(p_q, p_k, prior, out);
}